// round 8
// baseline (speedup 1.0000x reference)
#include <cuda_runtime.h>
#include <cstdint>
#include <cstddef>

#define BB 16
#define SS 4096
#define DD 256
#define CL 8
#define NROWW 16
#define NTHREADS 576          // wid0=G(+loader), wid1=S, wid2..17 = 16 row warps
#define RING 64
#define XD 8                  // x smem ring depth
#define LAGF 16               // fold application lag (steps)

typedef unsigned long long ull;

// per-(b,t): {q = c/alpha, P1 = x_t . x_{t+1}, d = 2*alpha*c + c^2*||x||^2, 0}
__device__ float4 g_f4[BB * SS + 16];
__device__ float  g_G0;       // ||M_init||_F^2

// ---------------- helpers --------------------------------------------------
__device__ __forceinline__ ull mul2(ull a, ull b) {
    ull d; asm("mul.rn.f32x2 %0,%1,%2;" : "=l"(d) : "l"(a), "l"(b)); return d;
}
__device__ __forceinline__ ull fma2(ull a, ull b, ull c) {
    ull d; asm("fma.rn.f32x2 %0,%1,%2,%3;" : "=l"(d) : "l"(a), "l"(b), "l"(c)); return d;
}
__device__ __forceinline__ void unpk(ull a, float& x, float& y) {
    asm("mov.b64 {%0,%1},%2;" : "=f"(x), "=f"(y) : "l"(a));
}
__device__ __forceinline__ ull pk(float lo, float hi) {
    ull d; asm("mov.b64 %0,{%1,%2};" : "=l"(d) : "f"(lo), "f"(hi)); return d;
}
__device__ __forceinline__ ull pack_fu(float v, unsigned tag) {
    return (ull)__float_as_uint(v) | ((ull)tag << 32);
}
__device__ __forceinline__ ull ldsv64(uint32_t a) {
    ull v; asm volatile("ld.volatile.shared.b64 %0,[%1];" : "=l"(v) : "r"(a) : "memory"); return v;
}
__device__ __forceinline__ void stsv64(uint32_t a, ull v) {
    asm volatile("st.volatile.shared.b64 [%0],%1;" :: "r"(a), "l"(v) : "memory");
}
__device__ __forceinline__ unsigned ldsv32(uint32_t a) {
    unsigned v; asm volatile("ld.volatile.shared.b32 %0,[%1];" : "=r"(v) : "r"(a) : "memory"); return v;
}
__device__ __forceinline__ void stsv32(uint32_t a, unsigned v) {
    asm volatile("st.volatile.shared.b32 [%0],%1;" :: "r"(a), "r"(v) : "memory");
}
__device__ __forceinline__ void stcl64(uint32_t a, ull v) {
    asm volatile("st.shared::cluster.b64 [%0],%1;" :: "r"(a), "l"(v) : "memory");
}
// tight spins — no nanosleep
__device__ __forceinline__ float poll_tag64(uint32_t a, unsigned want) {
    ull u = ldsv64(a);
    while ((unsigned)(u >> 32) != want) u = ldsv64(a);
    return __uint_as_float((unsigned)u);
}
__device__ __forceinline__ void poll_ge32(uint32_t a, int want) {
    while ((int)ldsv32(a) < want) { }
}
__device__ __forceinline__ void cpa16(uint32_t d, const void* s) {
    asm volatile("cp.async.ca.shared.global [%0],[%1],16;" :: "r"(d), "l"(s));
}
__device__ __forceinline__ float wredux(float v) {
    #pragma unroll
    for (int k = 16; k; k >>= 1) v += __shfl_xor_sync(0xffffffffu, v, k);
    return v;
}

// ---------------------------------------------------------------------------
__global__ void coef_kernel(const float* __restrict__ x,
                            const float* __restrict__ eta_raw,
                            const float* __restrict__ alpha_raw) {
    float eta   = 0.2f / (1.0f + __expf(-eta_raw[0]));
    float alpha = 0.5f + 0.5f / (1.0f + __expf(-alpha_raw[0]));
    int warp  = (blockIdx.x * blockDim.x + threadIdx.x) >> 5;
    int lane  = threadIdx.x & 31;
    int nwarp = (gridDim.x * blockDim.x) >> 5;
    for (int row = warp; row < BB * SS; row += nwarp) {
        int tloc = row & (SS - 1);
        const float4* xr  = reinterpret_cast<const float4*>(x + (size_t)row * DD);
        const float4* xr2 = (tloc == SS - 1) ? xr : xr + 64;   // x_{t+1} (clamped)
        float4 a = xr[lane],  b = xr[lane + 32];
        float4 c2 = xr2[lane], d2 = xr2[lane + 32];
        float ss = a.x*a.x + a.y*a.y + a.z*a.z + a.w*a.w
                 + b.x*b.x + b.y*b.y + b.z*b.z + b.w*b.w;
        float p1 = a.x*c2.x + a.y*c2.y + a.z*c2.z + a.w*c2.w
                 + b.x*d2.x + b.y*d2.y + b.z*d2.z + b.w*d2.w;
        ss = wredux(ss);
        p1 = wredux(p1);
        if (lane == 0) {
            float n   = fmaxf(sqrtf(ss), 1e-6f);
            float inv = 1.0f / n;
            float c   = eta * (1.0f - inv) * inv;
            float4 o;
            o.x = c / alpha;                          // q
            o.y = p1;                                 // P1
            o.z = 2.0f * alpha * c + c * c * ss;      // d
            o.w = 0.0f;
            g_f4[row] = o;
        }
    }
}

__global__ void g0_kernel(const float* __restrict__ M) {
    __shared__ float red[32];
    int tid = threadIdx.x;
    float s = 0.0f;
    for (int i = tid; i < DD * DD; i += 1024) { float v = M[i]; s = fmaf(v, v, s); }
    s = wredux(s);
    if ((tid & 31) == 0) red[tid >> 5] = s;
    __syncthreads();
    if (tid < 32) {
        float v = red[tid];
        v = wredux(v);
        if (tid == 0) g_G0 = v;
    }
}

// ---------------------------------------------------------------------------
// Persistent scan. 8-CTA cluster per batch.
//   wid 0 (G): cp.async-stages x_t + f4_t into smem rings (lead 7, publishes
//              xprog); gathers per-warp ||w||^2 partials, DSMEM-multicasts.
//   wid 1 (S): scalar (P,G,s) recurrence, coalesced outputs, fold factors.
//   wid 2-17 : row warps. Loop-carried chain broken via Gram correction:
//              w~_t = D_t(lead-2 matvec) + g'_{t-1} * P1[t-1];  g' = q * w~.
// ---------------------------------------------------------------------------
__global__ void __cluster_dims__(CL, 1, 1) __launch_bounds__(NTHREADS, 1)
scan_kernel(const float* __restrict__ x,
            const float* __restrict__ Minit,
            const float* __restrict__ alpha_raw,
            float* __restrict__ out) {
    __shared__ __align__(16) float  xs[XD][DD];     // 8 KB x ring
    __shared__ __align__(16) float4 f4s[XD];        // per-step scalars ring
    __shared__ ull wv[RING][32];      // {tag, w_row} (true scale)
    __shared__ ull zv[RING][NROWW];   // {tag, w0^2+w1^2}
    __shared__ ull cslot[RING][CL];   // {tag, CTA partial} (DSMEM in)
    __shared__ ull resf[8];           // {tag jj+1, fold factor}
    __shared__ ull finslot;           // {0x7fffffff, final pending scale}
    __shared__ unsigned xprog;        // staged-x progress: x_0..x_{v-1} ready

    unsigned rank; asm("mov.u32 %0, %%cluster_ctarank;" : "=r"(rank));
    int batch = blockIdx.x / CL;
    int tid   = threadIdx.x;
    int wid   = tid >> 5;
    int lane  = tid & 31;

    for (int i = tid; i < RING * 32;    i += NTHREADS) (&wv[0][0])[i]    = 0ull;
    for (int i = tid; i < RING * NROWW; i += NTHREADS) (&zv[0][0])[i]    = 0ull;
    for (int i = tid; i < RING * CL;    i += NTHREADS) (&cslot[0][0])[i] = 0ull;
    if (tid < 8)  resf[tid] = 0ull;
    if (tid == 0) { finslot = 0ull; xprog = 0u; }
    __syncthreads();
    asm volatile("barrier.cluster.arrive.aligned;" ::: "memory");
    asm volatile("barrier.cluster.wait.aligned;"   ::: "memory");

    float alpha = 0.5f + 0.5f / (1.0f + __expf(-alpha_raw[0]));

    uint32_t wv_b  = (uint32_t)__cvta_generic_to_shared(&wv[0][0]);
    uint32_t zv_b  = (uint32_t)__cvta_generic_to_shared(&zv[0][0]);
    uint32_t cs_b  = (uint32_t)__cvta_generic_to_shared(&cslot[0][0]);
    uint32_t rf_b  = (uint32_t)__cvta_generic_to_shared(&resf[0]);
    uint32_t fin_b = (uint32_t)__cvta_generic_to_shared(&finslot);
    uint32_t xp_b  = (uint32_t)__cvta_generic_to_shared(&xprog);

    if (wid >= 2) {
        // ===================== row warp =====================
        int rw  = wid - 2;
        int rg0 = (int)rank * 32 + rw * 2;

        ull m0[4], m1[4];
        {
            const ulonglong2* mp = (const ulonglong2*)Minit + (size_t)rg0 * 64;
            ulonglong2 v0 = mp[lane],      v1 = mp[32 + lane];
            m0[0] = v0.x; m0[1] = v0.y; m0[2] = v1.x; m0[3] = v1.y;
            v0 = mp[64 + lane]; v1 = mp[96 + lane];
            m1[0] = v0.x; m1[1] = v0.y; m1[2] = v1.x; m1[3] = v1.y;
        }
        const ulonglong2* xsp = (const ulonglong2*)&xs[0][0];  // slot s: [s*64+lane], [s*64+32+lane]

        uint32_t wv_me = wv_b + (uint32_t)(rw * 2) * 8u;
        uint32_t zv_me = zv_b + (uint32_t)rw * 8u;

        // prologue: x_0, x_1 -> xb[0], xb[1]; D_0, D_1
        ull xb[4][4];
        float Dpa[2], Dpb[2];
        poll_ge32(xp_b, 2);
        #pragma unroll
        for (int p = 0; p < 2; p++) {
            ulonglong2 v0 = xsp[p * 64 + lane], v1 = xsp[p * 64 + 32 + lane];
            xb[p][0] = v0.x; xb[p][1] = v0.y; xb[p][2] = v1.x; xb[p][3] = v1.y;
            ull a = mul2(m0[0], xb[p][0]);
            a = fma2(m0[1], xb[p][1], a); a = fma2(m0[2], xb[p][2], a); a = fma2(m0[3], xb[p][3], a);
            ull b = mul2(m1[0], xb[p][0]);
            b = fma2(m1[1], xb[p][1], b); b = fma2(m1[2], xb[p][2], b); b = fma2(m1[3], xb[p][3], b);
            float ax, ay, bx, by; unpk(a, ax, ay); unpk(b, bx, by);
            Dpa[p] = wredux(ax + ay);
            Dpb[p] = wredux(bx + by);
        }
        float corr_a = 0.0f, corr_b = 0.0f;
        float a_k = 1.0f;

        #pragma unroll 4
        for (int t = 0; t < SS; t++) {
            // stage-in: x_{t+2} and f4_t (poll then plain LDS; poll is the fence)
            poll_ge32(xp_b, t + 3);
            int sl2 = (t + 2) & (XD - 1);
            ulonglong2 v0 = xsp[sl2 * 64 + lane], v1 = xsp[sl2 * 64 + 32 + lane];
            int pb = (t + 2) & 3;
            xb[pb][0] = v0.x; xb[pb][1] = v0.y; xb[pb][2] = v1.x; xb[pb][3] = v1.y;
            float4 f4 = f4s[t & (XD - 1)];

            // finalize w~_t (scalar chain: 1 add)
            float wta = Dpa[t & 1] + corr_a;
            float wtb = Dpb[t & 1] + corr_b;
            float wat = a_k * wta, wbt = a_k * wtb;
            int slot = t & (RING - 1);
            if (lane == 0) {
                unsigned tg = (unsigned)(t + 1);
                stsv64(wv_me + (uint32_t)slot * 256u,      pack_fu(wat, tg));
                stsv64(wv_me + (uint32_t)slot * 256u + 8u, pack_fu(wbt, tg));
                stsv64(zv_me + (uint32_t)slot * (NROWW * 8u),
                       pack_fu(fmaf(wat, wat, wbt * wbt), tg));
            }
            a_k *= alpha;

            // g' = q * w~ ; corr for t+1 = g' * P1[t]
            float ga = f4.x * wta, gb = f4.x * wtb;
            corr_a = ga * f4.y;
            corr_b = gb * f4.y;

            // update m~ += g' * x_t  (before matvec => single-correction scheme)
            int cu = t & 3;
            ull g2a = pk(ga, ga), g2b = pk(gb, gb);
            #pragma unroll
            for (int j = 0; j < 4; j++) {
                m0[j] = fma2(g2a, xb[cu][j], m0[j]);
                m1[j] = fma2(g2b, xb[cu][j], m1[j]);
            }

            // lead-2 matvec: D_{t+2} = m~ . x_{t+2}
            ull a = mul2(m0[0], xb[pb][0]);
            a = fma2(m0[1], xb[pb][1], a); a = fma2(m0[2], xb[pb][2], a); a = fma2(m0[3], xb[pb][3], a);
            ull b = mul2(m1[0], xb[pb][0]);
            b = fma2(m1[1], xb[pb][1], b); b = fma2(m1[2], xb[pb][2], b); b = fma2(m1[3], xb[pb][3], b);
            float ax, ay, bx, by; unpk(a, ax, ay); unpk(b, bx, by);
            Dpa[t & 1] = wredux(ax + ay);
            Dpb[t & 1] = wredux(bx + by);

            // scheduled refactor: scale m~, both pendings, corr; reset a_k
            if ((t & 31) == 15 && t >= 47) {
                int jj = (t - 47) >> 5;
                float f = 0.0f;
                if (lane == 0)
                    f = poll_tag64(rf_b + (uint32_t)(jj & 7) * 8u, (unsigned)(jj + 1));
                f = __shfl_sync(0xffffffffu, f, 0);
                float F = f * a_k;
                ull F2 = pk(F, F);
                #pragma unroll
                for (int j = 0; j < 4; j++) { m0[j] = mul2(F2, m0[j]); m1[j] = mul2(F2, m1[j]); }
                Dpa[0] *= F; Dpa[1] *= F; Dpb[0] *= F; Dpb[1] *= F;
                corr_a *= F; corr_b *= F;
                a_k = 1.0f;
            }
        }
        // M_final = Pf * a_k * m~
        float Pf = 0.0f;
        if (lane == 0) Pf = poll_tag64(fin_b, 0x7fffffffu);
        Pf = __shfl_sync(0xffffffffu, Pf, 0);
        float fs = Pf * a_k;
        ull p2 = pk(fs, fs);
        ulonglong2* mo = (ulonglong2*)
            (out + (size_t)BB * SS * DD + (size_t)batch * DD * DD) + (size_t)rg0 * 64;
        ulonglong2 sv;
        sv.x = mul2(p2, m0[0]); sv.y = mul2(p2, m0[1]); mo[lane]      = sv;
        sv.x = mul2(p2, m0[2]); sv.y = mul2(p2, m0[3]); mo[32 + lane] = sv;
        sv.x = mul2(p2, m1[0]); sv.y = mul2(p2, m1[1]); mo[64 + lane] = sv;
        sv.x = mul2(p2, m1[2]); sv.y = mul2(p2, m1[3]); mo[96 + lane] = sv;

    } else if (wid == 0) {
        // ===================== G warp: x/f4 stager + zv gatherer ============
        const char*   xsrc = (const char*)(x + (size_t)batch * SS * DD);
        const float4* fsrc = g_f4 + (size_t)batch * SS;
        uint32_t xs_b = (uint32_t)__cvta_generic_to_shared(&xs[0][0]);
        uint32_t f4_b = (uint32_t)__cvta_generic_to_shared(&f4s[0]);
        uint32_t raddr = 0;
        {
            uint32_t cb2 = (uint32_t)__cvta_generic_to_shared(&cslot[0][rank]);
            if (lane < CL)
                asm("mapa.shared::cluster.u32 %0,%1,%2;" : "=r"(raddr) : "r"(cb2), "r"(lane));
        }
        // prologue: stage logical 0..6
        #pragma unroll
        for (int l = 0; l < 7; l++) {
            uint32_t dst = xs_b + (uint32_t)(l & (XD - 1)) * 1024u + (uint32_t)lane * 16u;
            const char* src = xsrc + (size_t)l * 1024 + lane * 16;
            cpa16(dst, src);
            cpa16(dst + 512u, src + 512);
            if (lane == 0) cpa16(f4_b + (uint32_t)(l & (XD - 1)) * 16u, fsrc + l);
            asm volatile("cp.async.commit_group;" ::: "memory");
        }
        asm volatile("cp.async.wait_group 4;" ::: "memory");
        asm volatile("membar.cta;" ::: "memory");
        if (lane == 0) stsv32(xp_b, 3u);

        for (int t = 0; t < SS; t++) {
            // stage logical t+7 (clamped)
            int l = t + 7; int ls = (l > SS - 1) ? SS - 1 : l;
            uint32_t dst = xs_b + (uint32_t)(l & (XD - 1)) * 1024u + (uint32_t)lane * 16u;
            const char* src = xsrc + (size_t)ls * 1024 + lane * 16;
            cpa16(dst, src);
            cpa16(dst + 512u, src + 512);
            if (lane == 0) cpa16(f4_b + (uint32_t)(l & (XD - 1)) * 16u, fsrc + ls);
            asm volatile("cp.async.commit_group;" ::: "memory");
            asm volatile("cp.async.wait_group 4;" ::: "memory");
            asm volatile("membar.cta;" ::: "memory");
            if (lane == 0) stsv32(xp_b, (unsigned)(t + 4));

            // zv gather + DSMEM multicast
            int slot = t & (RING - 1);
            float z = 0.0f;
            if (lane < NROWW)
                z = poll_tag64(zv_b + (uint32_t)(slot * NROWW + lane) * 8u, (unsigned)(t + 1));
            z = wredux(z);
            if (lane < CL)
                stcl64(raddr + (uint32_t)slot * (CL * 8u), pack_fu(z, (unsigned)(t + 1)));
        }

    } else {
        // ===================== S warp =====================
        const float* db = (const float*)(g_f4 + (size_t)batch * SS) + 2;  // d at [4t+2]
        float P = 1.0f, G = g_G0;
        float aa = alpha * alpha;
        float pend_f = 1.0f; int pend_mat = -1;
        float* outb = out + (size_t)batch * SS * DD + rank * 32 + lane;
        for (int tau = 0; tau < SS; tau++) {
            int slot = tau & (RING - 1);
            float w = poll_tag64(wv_b + (uint32_t)(slot * 32 + lane) * 8u, (unsigned)(tau + 1));
            float zc = 0.0f;
            if (lane < CL)
                zc = poll_tag64(cs_b + (uint32_t)(slot * CL + lane) * 8u, (unsigned)(tau + 1));
            zc = wredux(zc);      // replicated global ||w||^2
            float Qb = P;
            outb[(size_t)tau * DD] = Qb * w;
            float y2 = Qb * Qb * zc;
            float d  = __ldg(db + 4 * tau);
            float Gn = fmaf(aa, G, d * y2);
            float s  = fminf(15.0f / (sqrtf(Gn) + 1e-6f), 1.0f);
            G = s * s * Gn;
            P = Qb * s;
            if (tau == pend_mat) { P = P / pend_f; pend_mat = -1; }
            if ((tau & 31) == 31 && tau + LAGF <= SS - 1) {
                int jj = tau >> 5;
                pend_f = P;
                pend_mat = tau + LAGF;
                if (lane == 0)
                    stsv64(rf_b + (uint32_t)(jj & 7) * 8u, pack_fu(P, (unsigned)(jj + 1)));
            }
        }
        if (lane == 0) stsv64(fin_b, pack_fu(P, 0x7fffffffu));
    }
}

// ---------------------------------------------------------------------------
extern "C" void kernel_launch(void* const* d_in, const int* in_sizes, int n_in,
                              void* d_out, int out_size) {
    const float* x         = (const float*)d_in[0];
    const float* M_init    = (const float*)d_in[1];
    const float* eta_raw   = (const float*)d_in[2];
    const float* alpha_raw = (const float*)d_in[3];
    float*       out       = (float*)d_out;

    coef_kernel<<<1024, 256>>>(x, eta_raw, alpha_raw);
    g0_kernel<<<1, 1024>>>(M_init);
    scan_kernel<<<BB * CL, NTHREADS>>>(x, M_init, alpha_raw, out);
}